// round 14
// baseline (speedup 1.0000x reference)
#include <cuda_runtime.h>
#include <cuda_fp16.h>
#include <cstdint>

// ---------------------------------------------------------------------------
// HyperAttention on GB300 (sm_103 baseline PTX): mma.sync m16n8k16 flash
// attention, fixed-shift softmax (log2 domain).  B=2,H=16,N=8192,D=64.
// Pipeline: hash -> stable sort -> conv (sorted fp16 K/V) -> attention.
// attn CTA = 256 queries x 512 keys, 16 warps x 16 q-rows, cp.async loads.
// ---------------------------------------------------------------------------

#define BH      32
#define NSEQ    8192
#define DIM     64
#define NPROJ   7
#define NBUCK   128
#define NSEG    128
#define SEGLEN  64
#define ST      130
#define LOG32   3.4657359027997265f
#define BIGNEG  (-1e30f)
#define M_FIX   6.0f
#define LOG2E   1.4426950408889634f

__device__ unsigned char g_hash[2][BH * NSEQ];
__device__ int           g_idx[2][BH * NSEQ];   // [0]=q_idx, [1]=k_idx
__device__ __half        g_kh[(size_t)BH * NSEQ * DIM];   // sorted fp16 K
__device__ __half        g_vh[(size_t)BH * NSEQ * DIM];   // sorted fp16 V

// ===================== helpers =============================================
__device__ __forceinline__ uint32_t smem_u32(const void* p) {
    uint32_t a;
    asm("{ .reg .u64 t; cvta.to.shared.u64 t, %1; cvt.u32.u64 %0, t; }"
        : "=r"(a) : "l"(p));
    return a;
}
__device__ __forceinline__ uint32_t swz(uint32_t o) { return o ^ ((o >> 3) & 0x70); }

__device__ __forceinline__ float ex2f(float x) {
    float y; asm("ex2.approx.ftz.f32 %0, %1;" : "=f"(y) : "f"(x)); return y;
}
__device__ __forceinline__ void cpasync16(uint32_t d, const void* s) {
    asm volatile("cp.async.cg.shared.global [%0], [%1], 16;" :: "r"(d), "l"(s));
}
__device__ __forceinline__ void cpasync_commit() {
    asm volatile("cp.async.commit_group;" ::: "memory");
}
__device__ __forceinline__ void cpasync_wait0() {
    asm volatile("cp.async.wait_group 0;" ::: "memory");
}
__device__ __forceinline__ void mma16816(float* c, const uint32_t* a,
                                         uint32_t b0, uint32_t b1) {
    asm volatile(
        "mma.sync.aligned.m16n8k16.row.col.f32.f16.f16.f32 "
        "{%0,%1,%2,%3}, {%4,%5,%6,%7}, {%8,%9}, {%0,%1,%2,%3};"
        : "+f"(c[0]), "+f"(c[1]), "+f"(c[2]), "+f"(c[3])
        : "r"(a[0]), "r"(a[1]), "r"(a[2]), "r"(a[3]), "r"(b0), "r"(b1));
}
__device__ __forceinline__ void ldsm4(uint32_t* r, uint32_t addr) {
    asm volatile("ldmatrix.sync.aligned.m8n8.x4.shared.b16 {%0,%1,%2,%3}, [%4];"
        : "=r"(r[0]), "=r"(r[1]), "=r"(r[2]), "=r"(r[3]) : "r"(addr));
}
__device__ __forceinline__ void ldsm4t(uint32_t* r, uint32_t addr) {
    asm volatile("ldmatrix.sync.aligned.m8n8.x4.trans.shared.b16 {%0,%1,%2,%3}, [%4];"
        : "=r"(r[0]), "=r"(r[1]), "=r"(r[2]), "=r"(r[3]) : "r"(addr));
}

// ---------------------------------------------------------------------------
// LSH hash: 64-row q-tile + 64-row k-tile per CTA (validated, unchanged)
// ---------------------------------------------------------------------------
#define HROWS 64
__global__ __launch_bounds__(128)
void hash_kernel(const float* __restrict__ q,
                 const float* __restrict__ k,
                 const float* __restrict__ proj) {
    __shared__ float  pjs[NPROJ][DIM];
    __shared__ float4 buf[2][HROWS * 16];
    const int t = threadIdx.x;
    for (int i = t; i < DIM * NPROJ; i += 128)
        pjs[i % NPROJ][i / NPROJ] = proj[i];

    const float4* qs = (const float4*)q + (size_t)blockIdx.x * (HROWS * 16);
    const float4* ks = (const float4*)k + (size_t)blockIdx.x * (HROWS * 16);
    const uint32_t b0 = smem_u32(&buf[0][0]);
    const uint32_t b1 = smem_u32(&buf[1][0]);
    for (int i = t; i < HROWS * 16; i += 128) {
        const int row = i >> 4, u = i & 15;
        const uint32_t off = (uint32_t)(row * 16 + (u ^ (row & 7))) * 16u;
        cpasync16(b0 + off, qs + i);
        cpasync16(b1 + off, ks + i);
    }
    cpasync_commit();
    cpasync_wait0();
    __syncthreads();

    const int which = t >> 6;
    const int r0 = t & 63;
    const float4* mybuf = buf[which];

    float xr[DIM];
#pragma unroll
    for (int u = 0; u < 16; u++) {
        float4 f = mybuf[r0 * 16 + (u ^ (r0 & 7))];
        xr[4 * u] = f.x; xr[4 * u + 1] = f.y;
        xr[4 * u + 2] = f.z; xr[4 * u + 3] = f.w;
    }
    int code = 0;
#pragma unroll 1
    for (int r = 0; r < NPROJ; r++) {
        float a[32];
#pragma unroll
        for (int l = 0; l < 16; l++) {
            float4 p4 = *(const float4*)&pjs[r][4 * l];
            a[2 * l]     = xr[4 * l]     * p4.x + xr[4 * l + 1] * p4.y;
            a[2 * l + 1] = xr[4 * l + 2] * p4.z + xr[4 * l + 3] * p4.w;
        }
#pragma unroll
        for (int off = 16; off > 0; off >>= 1)
#pragma unroll
            for (int i = 0; i < 32; i++)
                if (i < off) a[i] += a[i + off];
        code |= (a[0] > 0.0f ? 1 : 0) << r;
    }
    g_hash[which][blockIdx.x * HROWS + r0] = (unsigned char)(code ^ (code >> 1));
}

// ---------------------------------------------------------------------------
// stable counting sort (validated, unchanged)
// ---------------------------------------------------------------------------
__global__ void sort_kernel() {
    __shared__ unsigned short seg[NSEG * ST];
    __shared__ int base[NBUCK];
    __shared__ int tot[NBUCK];
    const int which = blockIdx.x >> 5;
    const int bh = blockIdx.x & 31;
    const int t = threadIdx.x;
    const unsigned char* hp = g_hash[which] + bh * NSEQ;
    int* op = g_idx[which] + bh * NSEQ;

    uint32_t myb[16];
    {
        const uint4* p4 = (const uint4*)(hp + t * SEGLEN);
#pragma unroll
        for (int u = 0; u < 4; u++) {
            uint4 x = p4[u];
            myb[4 * u] = x.x; myb[4 * u + 1] = x.y;
            myb[4 * u + 2] = x.z; myb[4 * u + 3] = x.w;
        }
    }
    for (int i = t; i < NSEG * ST; i += NSEG) seg[i] = 0;
    __syncthreads();
    {
        unsigned short* row = seg + t * ST;
#pragma unroll 1
        for (int k2 = 0; k2 < SEGLEN; k2++) {
            int vv = (myb[k2 >> 2] >> ((k2 & 3) * 8)) & 0xff;
            row[vv]++;
        }
    }
    __syncthreads();
    {
        int run = 0;
        for (int s = 0; s < NSEG; s++) {
            int c = seg[s * ST + t];
            seg[s * ST + t] = (unsigned short)run;
            run += c;
        }
        tot[t] = run;
    }
    __syncthreads();
    if (t == 0) {
        int run = 0;
        for (int vv = 0; vv < NBUCK; vv++) { base[vv] = run; run += tot[vv]; }
    }
    __syncthreads();
    {
        unsigned short* row = seg + t * ST;
        const int b0 = t * SEGLEN;
#pragma unroll 1
        for (int k2 = 0; k2 < SEGLEN; k2++) {
            int vv = (myb[k2 >> 2] >> ((k2 & 3) * 8)) & 0xff;
            op[base[vv] + row[vv]] = b0 + k2;
            row[vv]++;
        }
    }
}

// ---------------------------------------------------------------------------
// conv: materialize sorted K/V as fp16 (validated, unchanged)
// ---------------------------------------------------------------------------
__global__ __launch_bounds__(256)
void conv_kernel(const float* __restrict__ k, const float* __restrict__ v) {
    const int bh = blockIdx.y;
    const int t = threadIdx.x;
    const int j = t >> 2, sub = t & 3;
    const int srow = blockIdx.x * 64 + j;
    const size_t bhBase = (size_t)bh * NSEQ;
    const int krow = g_idx[1][bhBase + srow];
    const float4* ks = (const float4*)(k + (bhBase + krow) * DIM + sub * 16);
    const float4* vs = (const float4*)(v + (bhBase + krow) * DIM + sub * 16);

    uint4* kd = (uint4*)(g_kh + (bhBase + srow) * DIM) + sub * 2;
    uint4* vd = (uint4*)(g_vh + (bhBase + srow) * DIM) + sub * 2;
#pragma unroll
    for (int hf = 0; hf < 2; hf++) {
        float4 a = ks[2 * hf], b = ks[2 * hf + 1];
        half2 h0 = __floats2half2_rn(a.x, a.y), h1 = __floats2half2_rn(a.z, a.w);
        half2 h2 = __floats2half2_rn(b.x, b.y), h3 = __floats2half2_rn(b.z, b.w);
        uint4 pk = {*(uint32_t*)&h0, *(uint32_t*)&h1, *(uint32_t*)&h2, *(uint32_t*)&h3};
        kd[hf] = pk;
        a = vs[2 * hf]; b = vs[2 * hf + 1];
        h0 = __floats2half2_rn(a.x, a.y); h1 = __floats2half2_rn(a.z, a.w);
        h2 = __floats2half2_rn(b.x, b.y); h3 = __floats2half2_rn(b.z, b.w);
        uint4 pv = {*(uint32_t*)&h0, *(uint32_t*)&h1, *(uint32_t*)&h2, *(uint32_t*)&h3};
        vd[hf] = pv;
    }
}

// ---------------------------------------------------------------------------
// fused attention: grid (32 qb, 32 bh), 512 threads (16 warps x 16 q-rows).
// K/V tiles via cp.async from pre-converted sorted fp16; double-buffered.
// ---------------------------------------------------------------------------
__global__ __launch_bounds__(512, 1)
void attn_kernel(const float* __restrict__ q, const int* __restrict__ sampled,
                 float* __restrict__ out) {
    __shared__ __align__(128) char KsmB[2 * 8192];
    __shared__ __align__(128) char VsmB[2 * 8192];
    __shared__ float addv[2][64];

    const int tid  = threadIdx.x;
    const int w    = tid >> 5;          // 0..15
    const int lane = tid & 31;
    const int qb   = blockIdx.x;
    const int bh   = blockIdx.y;
    const size_t bhBase = (size_t)bh * NSEQ;
    const int* qidx = g_idx[0] + bhBase;
    const int* smp  = sampled + bh * 256;

    const uint32_t Ksm = smem_u32(KsmB);
    const uint32_t Vsm = smem_u32(VsmB);

    // ---- Q fragments: warp w owns rows [16w, 16w+16) ----
    const int rt = 16 * w + (lane >> 2);
    const int qrow0 = qidx[qb * 256 + rt];
    const int qrow1 = qidx[qb * 256 + rt + 8];
    const float* q0p = q + (bhBase + qrow0) * DIM;
    const float* q1p = q + (bhBase + qrow1) * DIM;
    const float qsc = 0.125f * LOG2E;

    uint32_t qh[4][4];
#pragma unroll
    for (int s = 0; s < 4; s++) {
        const int d = 16 * s + (lane & 3) * 2;
        float2 f00 = *(const float2*)(q0p + d);
        float2 f10 = *(const float2*)(q1p + d);
        float2 f01 = *(const float2*)(q0p + d + 8);
        float2 f11 = *(const float2*)(q1p + d + 8);
        half2 h;
        h = __floats2half2_rn(f00.x * qsc, f00.y * qsc); qh[s][0] = *(uint32_t*)&h;
        h = __floats2half2_rn(f10.x * qsc, f10.y * qsc); qh[s][1] = *(uint32_t*)&h;
        h = __floats2half2_rn(f01.x * qsc, f01.y * qsc); qh[s][2] = *(uint32_t*)&h;
        h = __floats2half2_rn(f11.x * qsc, f11.y * qsc); qh[s][3] = *(uint32_t*)&h;
    }

    // ---- load lane mapping: 8 threads per key row, 16B pieces ----
    const int j   = tid >> 3;          // key row 0..63
    const int sub = tid & 7;           // 16B piece (8 halfs)

    float O[8][4];
#pragma unroll
    for (int g = 0; g < 8; g++)
#pragma unroll
        for (int e = 0; e < 4; e++) O[g][e] = 0.0f;
    float lsum0 = 0.0f, lsum1 = 0.0f;

    // ---- issue chunk 0 ----
    {
        const int srow = qb * 256 + j;
        const __half* ksrc = g_kh + (bhBase + srow) * DIM + sub * 8;
        const __half* vsrc = g_vh + (bhBase + srow) * DIM + sub * 8;
        const uint32_t o0 = swz((uint32_t)(j * 128 + sub * 16));
        cpasync16(Ksm + o0, ksrc);
        cpasync16(Vsm + o0, vsrc);
        if (sub == 0) addv[0][j] = -M_FIX * LOG2E;
        cpasync_commit();
    }
    cpasync_wait0();
    __syncthreads();

#pragma unroll 1
    for (int c = 0; c < 8; c++) {
        // ---- issue chunk c+1 into the other buffer ----
        if (c < 7) {
            const int kk = (c + 1) * 64 + j;
            int srow; float ad;
            if (kk < 256) { srow = qb * 256 + kk; ad = -M_FIX * LOG2E; }
            else {
                int sj = smp[kk - 256];
                srow = sj;
                ad = ((sj >> 8) == qb) ? BIGNEG : ((LOG32 - M_FIX) * LOG2E);
            }
            const __half* ksrc = g_kh + (bhBase + srow) * DIM + sub * 8;
            const __half* vsrc = g_vh + (bhBase + srow) * DIM + sub * 8;
            const uint32_t bb = (uint32_t)((c + 1) & 1) * 8192;
            const uint32_t o0 = bb + swz((uint32_t)(j * 128 + sub * 16));
            cpasync16(Ksm + o0, ksrc);
            cpasync16(Vsm + o0, vsrc);
            if (sub == 0) addv[(c + 1) & 1][j] = ad;
            cpasync_commit();
        }

        const uint32_t Kb = Ksm + (uint32_t)(c & 1) * 8192;
        const uint32_t Vb = Vsm + (uint32_t)(c & 1) * 8192;
        const float* av = addv[c & 1];

        // ---- S = Q.K^T + fused softmax -> P fragments ----
        uint32_t P01[8], P23[8];
#pragma unroll
        for (int g = 0; g < 8; g++) {
            uint32_t kb[8];
            const uint32_t key = 8u * g + (lane & 7);
            const uint32_t dv  = ((uint32_t)(lane >> 3) & 3u) * 8u;
            ldsm4(kb,     Kb + swz(key * 128 + dv * 2));
            ldsm4(kb + 4, Kb + swz(key * 128 + (32 + dv) * 2));
            const int n0 = 8 * g + (lane & 3) * 2;
            const float av0 = av[n0], av1 = av[n0 + 1];
            float S[4] = {0.0f, 0.0f, 0.0f, 0.0f};
#pragma unroll
            for (int s = 0; s < 4; s++)
                mma16816(S, qh[s], kb[2 * s], kb[2 * s + 1]);
            float e0 = ex2f(S[0] + av0);
            float e1 = ex2f(S[1] + av1);
            float e2 = ex2f(S[2] + av0);
            float e3 = ex2f(S[3] + av1);
            lsum0 += e0 + e1;
            lsum1 += e2 + e3;
            half2 h01 = __floats2half2_rn(e0, e1);
            half2 h23 = __floats2half2_rn(e2, e3);
            P01[g] = *(uint32_t*)&h01;
            P23[g] = *(uint32_t*)&h23;
        }

        // ---- O += P . V ----
#pragma unroll
        for (int jj = 0; jj < 4; jj++) {
            uint32_t A[4] = {P01[2 * jj], P23[2 * jj], P01[2 * jj + 1], P23[2 * jj + 1]};
            const uint32_t key = 16u * jj + ((uint32_t)lane & 15u);
            const uint32_t dof = ((uint32_t)(lane >> 4) & 1u) * 8u;
#pragma unroll
            for (int dg = 0; dg < 4; dg++) {
                uint32_t vb[4];
                ldsm4t(vb, Vb + swz(key * 128 + (16u * dg + dof) * 2));
                mma16816(O[2 * dg],     A, vb[0], vb[1]);
                mma16816(O[2 * dg + 1], A, vb[2], vb[3]);
            }
        }

        if (c < 7) cpasync_wait0();
        __syncthreads();
    }

    // ---- epilogue ----
    lsum0 += __shfl_xor_sync(0xffffffffu, lsum0, 1);
    lsum0 += __shfl_xor_sync(0xffffffffu, lsum0, 2);
    lsum1 += __shfl_xor_sync(0xffffffffu, lsum1, 1);
    lsum1 += __shfl_xor_sync(0xffffffffu, lsum1, 2);
    const float inv0 = 1.0f / lsum0;
    const float inv1 = 1.0f / lsum1;

    float* o0p = out + (bhBase + qrow0) * DIM;
    float* o1p = out + (bhBase + qrow1) * DIM;
#pragma unroll
    for (int g = 0; g < 8; g++) {
        const int n0 = 8 * g + (lane & 3) * 2;
        float2 a = {O[g][0] * inv0, O[g][1] * inv0};
        float2 b = {O[g][2] * inv1, O[g][3] * inv1};
        *(float2*)(o0p + n0) = a;
        *(float2*)(o1p + n0) = b;
    }
}

// ---------------------------------------------------------------------------
extern "C" void kernel_launch(void* const* d_in, const int* in_sizes, int n_in,
                              void* d_out, int out_size) {
    (void)in_sizes; (void)n_in; (void)out_size;
    const float* q    = (const float*)d_in[0];
    const float* k    = (const float*)d_in[1];
    const float* v    = (const float*)d_in[2];
    const float* proj = (const float*)d_in[3];
    const int*   smp  = (const int*)d_in[4];
    float* out = (float*)d_out;

    hash_kernel<<<(BH * NSEQ) / HROWS, 128>>>(q, k, proj);
    sort_kernel<<<64, 128>>>();
    conv_kernel<<<dim3(NSEQ / 64, BH), 256>>>(k, v);
    attn_kernel<<<dim3(32, 32), 512>>>(q, smp, out);
}

// round 16
// speedup vs baseline: 1.0702x; 1.0702x over previous
#include <cuda_runtime.h>
#include <cuda_fp16.h>
#include <cstdint>

// ---------------------------------------------------------------------------
// HyperAttention on GB300 (sm_103 baseline PTX): mma.sync m16n8k16 flash
// attention, fixed-shift softmax (log2 domain).  B=2,H=16,N=8192,D=64.
// Pipeline: hash -> stable sort -> conv (sorted fp16 K/V) -> attention.
// attn CTA = 128 queries x 512 keys, 4 warps x 32 q-rows, 2 CTAs/SM.
// ---------------------------------------------------------------------------

#define BH      32
#define NSEQ    8192
#define DIM     64
#define NPROJ   7
#define NBUCK   128
#define NSEG    128
#define SEGLEN  64
#define ST      130
#define LOG32   3.4657359027997265f
#define BIGNEG  (-1e30f)
#define M_FIX   6.0f
#define LOG2E   1.4426950408889634f

__device__ unsigned char g_hash[2][BH * NSEQ];
__device__ int           g_idx[2][BH * NSEQ];   // [0]=q_idx, [1]=k_idx
__device__ __half        g_kh[(size_t)BH * NSEQ * DIM];   // sorted fp16 K
__device__ __half        g_vh[(size_t)BH * NSEQ * DIM];   // sorted fp16 V

// ===================== helpers =============================================
__device__ __forceinline__ uint32_t smem_u32(const void* p) {
    uint32_t a;
    asm("{ .reg .u64 t; cvta.to.shared.u64 t, %1; cvt.u32.u64 %0, t; }"
        : "=r"(a) : "l"(p));
    return a;
}
__device__ __forceinline__ uint32_t swz(uint32_t o) { return o ^ ((o >> 3) & 0x70); }

__device__ __forceinline__ float ex2f(float x) {
    float y; asm("ex2.approx.ftz.f32 %0, %1;" : "=f"(y) : "f"(x)); return y;
}
__device__ __forceinline__ void cpasync16(uint32_t d, const void* s) {
    asm volatile("cp.async.cg.shared.global [%0], [%1], 16;" :: "r"(d), "l"(s));
}
__device__ __forceinline__ void cpasync_commit() {
    asm volatile("cp.async.commit_group;" ::: "memory");
}
__device__ __forceinline__ void cpasync_wait0() {
    asm volatile("cp.async.wait_group 0;" ::: "memory");
}
__device__ __forceinline__ void mma16816(float* c, const uint32_t* a,
                                         uint32_t b0, uint32_t b1) {
    asm volatile(
        "mma.sync.aligned.m16n8k16.row.col.f32.f16.f16.f32 "
        "{%0,%1,%2,%3}, {%4,%5,%6,%7}, {%8,%9}, {%0,%1,%2,%3};"
        : "+f"(c[0]), "+f"(c[1]), "+f"(c[2]), "+f"(c[3])
        : "r"(a[0]), "r"(a[1]), "r"(a[2]), "r"(a[3]), "r"(b0), "r"(b1));
}
__device__ __forceinline__ void ldsm4(uint32_t* r, uint32_t addr) {
    asm volatile("ldmatrix.sync.aligned.m8n8.x4.shared.b16 {%0,%1,%2,%3}, [%4];"
        : "=r"(r[0]), "=r"(r[1]), "=r"(r[2]), "=r"(r[3]) : "r"(addr));
}
__device__ __forceinline__ void ldsm4t(uint32_t* r, uint32_t addr) {
    asm volatile("ldmatrix.sync.aligned.m8n8.x4.trans.shared.b16 {%0,%1,%2,%3}, [%4];"
        : "=r"(r[0]), "=r"(r[1]), "=r"(r[2]), "=r"(r[3]) : "r"(addr));
}

// ---------------------------------------------------------------------------
// LSH hash: 64-row q-tile + 64-row k-tile per CTA (validated, unchanged)
// ---------------------------------------------------------------------------
#define HROWS 64
__global__ __launch_bounds__(128)
void hash_kernel(const float* __restrict__ q,
                 const float* __restrict__ k,
                 const float* __restrict__ proj) {
    __shared__ float  pjs[NPROJ][DIM];
    __shared__ float4 buf[2][HROWS * 16];
    const int t = threadIdx.x;
    for (int i = t; i < DIM * NPROJ; i += 128)
        pjs[i % NPROJ][i / NPROJ] = proj[i];

    const float4* qs = (const float4*)q + (size_t)blockIdx.x * (HROWS * 16);
    const float4* ks = (const float4*)k + (size_t)blockIdx.x * (HROWS * 16);
    const uint32_t b0 = smem_u32(&buf[0][0]);
    const uint32_t b1 = smem_u32(&buf[1][0]);
    for (int i = t; i < HROWS * 16; i += 128) {
        const int row = i >> 4, u = i & 15;
        const uint32_t off = (uint32_t)(row * 16 + (u ^ (row & 7))) * 16u;
        cpasync16(b0 + off, qs + i);
        cpasync16(b1 + off, ks + i);
    }
    cpasync_commit();
    cpasync_wait0();
    __syncthreads();

    const int which = t >> 6;
    const int r0 = t & 63;
    const float4* mybuf = buf[which];

    float xr[DIM];
#pragma unroll
    for (int u = 0; u < 16; u++) {
        float4 f = mybuf[r0 * 16 + (u ^ (r0 & 7))];
        xr[4 * u] = f.x; xr[4 * u + 1] = f.y;
        xr[4 * u + 2] = f.z; xr[4 * u + 3] = f.w;
    }
    int code = 0;
#pragma unroll 1
    for (int r = 0; r < NPROJ; r++) {
        float a[32];
#pragma unroll
        for (int l = 0; l < 16; l++) {
            float4 p4 = *(const float4*)&pjs[r][4 * l];
            a[2 * l]     = xr[4 * l]     * p4.x + xr[4 * l + 1] * p4.y;
            a[2 * l + 1] = xr[4 * l + 2] * p4.z + xr[4 * l + 3] * p4.w;
        }
#pragma unroll
        for (int off = 16; off > 0; off >>= 1)
#pragma unroll
            for (int i = 0; i < 32; i++)
                if (i < off) a[i] += a[i + off];
        code |= (a[0] > 0.0f ? 1 : 0) << r;
    }
    g_hash[which][blockIdx.x * HROWS + r0] = (unsigned char)(code ^ (code >> 1));
}

// ---------------------------------------------------------------------------
// stable counting sort (validated, unchanged)
// ---------------------------------------------------------------------------
__global__ void sort_kernel() {
    __shared__ unsigned short seg[NSEG * ST];
    __shared__ int base[NBUCK];
    __shared__ int tot[NBUCK];
    const int which = blockIdx.x >> 5;
    const int bh = blockIdx.x & 31;
    const int t = threadIdx.x;
    const unsigned char* hp = g_hash[which] + bh * NSEQ;
    int* op = g_idx[which] + bh * NSEQ;

    uint32_t myb[16];
    {
        const uint4* p4 = (const uint4*)(hp + t * SEGLEN);
#pragma unroll
        for (int u = 0; u < 4; u++) {
            uint4 x = p4[u];
            myb[4 * u] = x.x; myb[4 * u + 1] = x.y;
            myb[4 * u + 2] = x.z; myb[4 * u + 3] = x.w;
        }
    }
    for (int i = t; i < NSEG * ST; i += NSEG) seg[i] = 0;
    __syncthreads();
    {
        unsigned short* row = seg + t * ST;
#pragma unroll 1
        for (int k2 = 0; k2 < SEGLEN; k2++) {
            int vv = (myb[k2 >> 2] >> ((k2 & 3) * 8)) & 0xff;
            row[vv]++;
        }
    }
    __syncthreads();
    {
        int run = 0;
        for (int s = 0; s < NSEG; s++) {
            int c = seg[s * ST + t];
            seg[s * ST + t] = (unsigned short)run;
            run += c;
        }
        tot[t] = run;
    }
    __syncthreads();
    if (t == 0) {
        int run = 0;
        for (int vv = 0; vv < NBUCK; vv++) { base[vv] = run; run += tot[vv]; }
    }
    __syncthreads();
    {
        unsigned short* row = seg + t * ST;
        const int b0 = t * SEGLEN;
#pragma unroll 1
        for (int k2 = 0; k2 < SEGLEN; k2++) {
            int vv = (myb[k2 >> 2] >> ((k2 & 3) * 8)) & 0xff;
            op[base[vv] + row[vv]] = b0 + k2;
            row[vv]++;
        }
    }
}

// ---------------------------------------------------------------------------
// conv: materialize sorted K/V as fp16 (validated, unchanged)
// ---------------------------------------------------------------------------
__global__ __launch_bounds__(256)
void conv_kernel(const float* __restrict__ k, const float* __restrict__ v) {
    const int bh = blockIdx.y;
    const int t = threadIdx.x;
    const int j = t >> 2, sub = t & 3;
    const int srow = blockIdx.x * 64 + j;
    const size_t bhBase = (size_t)bh * NSEQ;
    const int krow = g_idx[1][bhBase + srow];
    const float4* ks = (const float4*)(k + (bhBase + krow) * DIM + sub * 16);
    const float4* vs = (const float4*)(v + (bhBase + krow) * DIM + sub * 16);

    uint4* kd = (uint4*)(g_kh + (bhBase + srow) * DIM) + sub * 2;
    uint4* vd = (uint4*)(g_vh + (bhBase + srow) * DIM) + sub * 2;
#pragma unroll
    for (int hf = 0; hf < 2; hf++) {
        float4 a = ks[2 * hf], b = ks[2 * hf + 1];
        half2 h0 = __floats2half2_rn(a.x, a.y), h1 = __floats2half2_rn(a.z, a.w);
        half2 h2 = __floats2half2_rn(b.x, b.y), h3 = __floats2half2_rn(b.z, b.w);
        uint4 pk = {*(uint32_t*)&h0, *(uint32_t*)&h1, *(uint32_t*)&h2, *(uint32_t*)&h3};
        kd[hf] = pk;
        a = vs[2 * hf]; b = vs[2 * hf + 1];
        h0 = __floats2half2_rn(a.x, a.y); h1 = __floats2half2_rn(a.z, a.w);
        h2 = __floats2half2_rn(b.x, b.y); h3 = __floats2half2_rn(b.z, b.w);
        uint4 pv = {*(uint32_t*)&h0, *(uint32_t*)&h1, *(uint32_t*)&h2, *(uint32_t*)&h3};
        vd[hf] = pv;
    }
}

// ---------------------------------------------------------------------------
// fused attention: grid (64 q-halves, 32 bh), 128 threads (4 warps x 32 rows).
// 2 CTAs/SM for cross-CTA latency hiding; per-warp shape = round-13 winner.
// K/V tiles via cp.async from pre-converted sorted fp16; double-buffered.
// ---------------------------------------------------------------------------
__global__ __launch_bounds__(128, 2)
void attn_kernel(const float* __restrict__ q, const int* __restrict__ sampled,
                 float* __restrict__ out) {
    __shared__ __align__(128) char KsmB[2 * 8192];
    __shared__ __align__(128) char VsmB[2 * 8192];
    __shared__ float addv[2][64];

    const int tid  = threadIdx.x;
    const int w    = tid >> 5;          // 0..3
    const int lane = tid & 31;
    const int qh2  = blockIdx.x;        // 0..63 (128-query half-block)
    const int qb   = qh2 >> 1;          // sorted key block
    const int bh   = blockIdx.y;
    const size_t bhBase = (size_t)bh * NSEQ;
    const int* qidx = g_idx[0] + bhBase;
    const int* smp  = sampled + bh * 256;

    const uint32_t Ksm = smem_u32(KsmB);
    const uint32_t Vsm = smem_u32(VsmB);

    // ---- Q fragments: warp w owns rows [32w, 32w+32): tiles t0, t1 ----
    const int rt = 32 * w + (lane >> 2);
    int qrow[2][2];
    qrow[0][0] = qidx[qh2 * 128 + rt];
    qrow[0][1] = qidx[qh2 * 128 + rt + 8];
    qrow[1][0] = qidx[qh2 * 128 + rt + 16];
    qrow[1][1] = qidx[qh2 * 128 + rt + 24];
    const float qsc = 0.125f * LOG2E;

    uint32_t qh[2][4][4];
#pragma unroll
    for (int tt = 0; tt < 2; tt++) {
        const float* q0p = q + (bhBase + qrow[tt][0]) * DIM;
        const float* q1p = q + (bhBase + qrow[tt][1]) * DIM;
#pragma unroll
        for (int s = 0; s < 4; s++) {
            const int d = 16 * s + (lane & 3) * 2;
            float2 f00 = *(const float2*)(q0p + d);
            float2 f10 = *(const float2*)(q1p + d);
            float2 f01 = *(const float2*)(q0p + d + 8);
            float2 f11 = *(const float2*)(q1p + d + 8);
            half2 h;
            h = __floats2half2_rn(f00.x * qsc, f00.y * qsc); qh[tt][s][0] = *(uint32_t*)&h;
            h = __floats2half2_rn(f10.x * qsc, f10.y * qsc); qh[tt][s][1] = *(uint32_t*)&h;
            h = __floats2half2_rn(f01.x * qsc, f01.y * qsc); qh[tt][s][2] = *(uint32_t*)&h;
            h = __floats2half2_rn(f11.x * qsc, f11.y * qsc); qh[tt][s][3] = *(uint32_t*)&h;
        }
    }

    // ---- load lane mapping: 2 threads per key row, 64B halves ----
    const int j   = tid >> 1;          // key row 0..63
    const int sub = tid & 1;           // 64B half (32 halfs)

    float O[2][8][4];
#pragma unroll
    for (int tt = 0; tt < 2; tt++)
#pragma unroll
        for (int g = 0; g < 8; g++)
#pragma unroll
            for (int e = 0; e < 4; e++) O[tt][g][e] = 0.0f;
    float lsum[2][2] = {{0.0f, 0.0f}, {0.0f, 0.0f}};

    // ---- issue chunk 0 ----
    {
        const int srow = qb * 256 + j;
        const __half* ksrc = g_kh + (bhBase + srow) * DIM + sub * 32;
        const __half* vsrc = g_vh + (bhBase + srow) * DIM + sub * 32;
#pragma unroll
        for (int u = 0; u < 4; u++) {
            const uint32_t o0 = swz((uint32_t)(j * 128 + sub * 64 + u * 16));
            cpasync16(Ksm + o0, ksrc + u * 8);
            cpasync16(Vsm + o0, vsrc + u * 8);
        }
        if (sub == 0) addv[0][j] = -M_FIX * LOG2E;
        cpasync_commit();
    }
    cpasync_wait0();
    __syncthreads();

#pragma unroll 1
    for (int c = 0; c < 8; c++) {
        // ---- issue chunk c+1 into the other buffer ----
        if (c < 7) {
            const int kk = (c + 1) * 64 + j;
            int srow; float ad;
            if (kk < 256) { srow = qb * 256 + kk; ad = -M_FIX * LOG2E; }
            else {
                int sj = smp[kk - 256];
                srow = sj;
                ad = ((sj >> 8) == qb) ? BIGNEG : ((LOG32 - M_FIX) * LOG2E);
            }
            const __half* ksrc = g_kh + (bhBase + srow) * DIM + sub * 32;
            const __half* vsrc = g_vh + (bhBase + srow) * DIM + sub * 32;
            const uint32_t bb = (uint32_t)((c + 1) & 1) * 8192;
#pragma unroll
            for (int u = 0; u < 4; u++) {
                const uint32_t o0 = bb + swz((uint32_t)(j * 128 + sub * 64 + u * 16));
                cpasync16(Ksm + o0, ksrc + u * 8);
                cpasync16(Vsm + o0, vsrc + u * 8);
            }
            if (sub == 0) addv[(c + 1) & 1][j] = ad;
            cpasync_commit();
        }

        const uint32_t Kb = Ksm + (uint32_t)(c & 1) * 8192;
        const uint32_t Vb = Vsm + (uint32_t)(c & 1) * 8192;
        const float* av = addv[c & 1];

        // ---- S = Q.K^T + fused softmax -> P fragments (both tiles) ----
        uint32_t P01[2][8], P23[2][8];
#pragma unroll
        for (int g = 0; g < 8; g++) {
            uint32_t kb[8];
            const uint32_t key = 8u * g + (lane & 7);
            const uint32_t dv  = ((uint32_t)(lane >> 3) & 3u) * 8u;
            ldsm4(kb,     Kb + swz(key * 128 + dv * 2));
            ldsm4(kb + 4, Kb + swz(key * 128 + (32 + dv) * 2));
            const int n0 = 8 * g + (lane & 3) * 2;
            const float av0 = av[n0], av1 = av[n0 + 1];
#pragma unroll
            for (int tt = 0; tt < 2; tt++) {
                float S[4] = {0.0f, 0.0f, 0.0f, 0.0f};
#pragma unroll
                for (int s = 0; s < 4; s++)
                    mma16816(S, qh[tt][s], kb[2 * s], kb[2 * s + 1]);
                float e0 = ex2f(S[0] + av0);
                float e1 = ex2f(S[1] + av1);
                float e2 = ex2f(S[2] + av0);
                float e3 = ex2f(S[3] + av1);
                lsum[tt][0] += e0 + e1;
                lsum[tt][1] += e2 + e3;
                half2 h01 = __floats2half2_rn(e0, e1);
                half2 h23 = __floats2half2_rn(e2, e3);
                P01[tt][g] = *(uint32_t*)&h01;
                P23[tt][g] = *(uint32_t*)&h23;
            }
        }

        // ---- O += P . V  (V fragments shared across both tiles) ----
#pragma unroll
        for (int jj = 0; jj < 4; jj++) {
            const uint32_t key = 16u * jj + ((uint32_t)lane & 15u);
            const uint32_t dof = ((uint32_t)(lane >> 4) & 1u) * 8u;
            uint32_t A0[4] = {P01[0][2 * jj], P23[0][2 * jj],
                              P01[0][2 * jj + 1], P23[0][2 * jj + 1]};
            uint32_t A1[4] = {P01[1][2 * jj], P23[1][2 * jj],
                              P01[1][2 * jj + 1], P23[1][2 * jj + 1]};
#pragma unroll
            for (int dg = 0; dg < 4; dg++) {
                uint32_t vb[4];
                ldsm4t(vb, Vb + swz(key * 128 + (16u * dg + dof) * 2));
                mma16816(O[0][2 * dg],     A0, vb[0], vb[1]);
                mma16816(O[0][2 * dg + 1], A0, vb[2], vb[3]);
                mma16816(O[1][2 * dg],     A1, vb[0], vb[1]);
                mma16816(O[1][2 * dg + 1], A1, vb[2], vb[3]);
            }
        }

        if (c < 7) cpasync_wait0();
        __syncthreads();
    }

    // ---- epilogue ----
#pragma unroll
    for (int tt = 0; tt < 2; tt++) {
        float l0 = lsum[tt][0], l1 = lsum[tt][1];
        l0 += __shfl_xor_sync(0xffffffffu, l0, 1);
        l0 += __shfl_xor_sync(0xffffffffu, l0, 2);
        l1 += __shfl_xor_sync(0xffffffffu, l1, 1);
        l1 += __shfl_xor_sync(0xffffffffu, l1, 2);
        const float inv0 = 1.0f / l0;
        const float inv1 = 1.0f / l1;
        float* o0p = out + (bhBase + qrow[tt][0]) * DIM;
        float* o1p = out + (bhBase + qrow[tt][1]) * DIM;
#pragma unroll
        for (int g = 0; g < 8; g++) {
            const int n0 = 8 * g + (lane & 3) * 2;
            float2 a = {O[tt][g][0] * inv0, O[tt][g][1] * inv0};
            float2 b = {O[tt][g][2] * inv1, O[tt][g][3] * inv1};
            *(float2*)(o0p + n0) = a;
            *(float2*)(o1p + n0) = b;
        }
    }
}

// ---------------------------------------------------------------------------
extern "C" void kernel_launch(void* const* d_in, const int* in_sizes, int n_in,
                              void* d_out, int out_size) {
    (void)in_sizes; (void)n_in; (void)out_size;
    const float* q    = (const float*)d_in[0];
    const float* k    = (const float*)d_in[1];
    const float* v    = (const float*)d_in[2];
    const float* proj = (const float*)d_in[3];
    const int*   smp  = (const int*)d_in[4];
    float* out = (float*)d_out;

    hash_kernel<<<(BH * NSEQ) / HROWS, 128>>>(q, k, proj);
    sort_kernel<<<64, 128>>>();
    conv_kernel<<<dim3(NSEQ / 64, BH), 256>>>(k, v);
    attn_kernel<<<dim3(64, 32), 128>>>(q, smp, out);
}

// round 17
// speedup vs baseline: 1.0721x; 1.0018x over previous
#include <cuda_runtime.h>
#include <cuda_fp16.h>
#include <cstdint>

// ---------------------------------------------------------------------------
// HyperAttention on GB300 (sm_103 baseline PTX): mma.sync m16n8k16 flash
// attention, fixed-shift softmax (log2 domain).  B=2,H=16,N=8192,D=64.
// Pipeline: hash -> stable sort -> conv (sorted fp16 K/V) -> attention.
// attn CTA = 128 queries x 512 keys, 4 warps x 32 q-rows, 2 CTAs/SM,
// S/softmax/PV interleaved per 16-key step.
// ---------------------------------------------------------------------------

#define BH      32
#define NSEQ    8192
#define DIM     64
#define NPROJ   7
#define NBUCK   128
#define NSEG    128
#define SEGLEN  64
#define ST      130
#define LOG32   3.4657359027997265f
#define BIGNEG  (-1e30f)
#define M_FIX   6.0f
#define LOG2E   1.4426950408889634f

__device__ unsigned char g_hash[2][BH * NSEQ];
__device__ int           g_idx[2][BH * NSEQ];   // [0]=q_idx, [1]=k_idx
__device__ __half        g_kh[(size_t)BH * NSEQ * DIM];   // sorted fp16 K
__device__ __half        g_vh[(size_t)BH * NSEQ * DIM];   // sorted fp16 V

// ===================== helpers =============================================
__device__ __forceinline__ uint32_t smem_u32(const void* p) {
    uint32_t a;
    asm("{ .reg .u64 t; cvta.to.shared.u64 t, %1; cvt.u32.u64 %0, t; }"
        : "=r"(a) : "l"(p));
    return a;
}
__device__ __forceinline__ uint32_t swz(uint32_t o) { return o ^ ((o >> 3) & 0x70); }

__device__ __forceinline__ float ex2f(float x) {
    float y; asm("ex2.approx.ftz.f32 %0, %1;" : "=f"(y) : "f"(x)); return y;
}
__device__ __forceinline__ void cpasync16(uint32_t d, const void* s) {
    asm volatile("cp.async.cg.shared.global [%0], [%1], 16;" :: "r"(d), "l"(s));
}
__device__ __forceinline__ void cpasync_commit() {
    asm volatile("cp.async.commit_group;" ::: "memory");
}
__device__ __forceinline__ void cpasync_wait0() {
    asm volatile("cp.async.wait_group 0;" ::: "memory");
}
__device__ __forceinline__ void mma16816(float* c, const uint32_t* a,
                                         uint32_t b0, uint32_t b1) {
    asm volatile(
        "mma.sync.aligned.m16n8k16.row.col.f32.f16.f16.f32 "
        "{%0,%1,%2,%3}, {%4,%5,%6,%7}, {%8,%9}, {%0,%1,%2,%3};"
        : "+f"(c[0]), "+f"(c[1]), "+f"(c[2]), "+f"(c[3])
        : "r"(a[0]), "r"(a[1]), "r"(a[2]), "r"(a[3]), "r"(b0), "r"(b1));
}
__device__ __forceinline__ void ldsm4(uint32_t* r, uint32_t addr) {
    asm volatile("ldmatrix.sync.aligned.m8n8.x4.shared.b16 {%0,%1,%2,%3}, [%4];"
        : "=r"(r[0]), "=r"(r[1]), "=r"(r[2]), "=r"(r[3]) : "r"(addr));
}
__device__ __forceinline__ void ldsm4t(uint32_t* r, uint32_t addr) {
    asm volatile("ldmatrix.sync.aligned.m8n8.x4.trans.shared.b16 {%0,%1,%2,%3}, [%4];"
        : "=r"(r[0]), "=r"(r[1]), "=r"(r[2]), "=r"(r[3]) : "r"(addr));
}

// ---------------------------------------------------------------------------
// LSH hash: 32-row q-tile + 32-row k-tile per CTA, 64 threads (18KB smem ->
// ~12 CTAs/SM for deep load/compute overlap).  Per-row compute BIT-EXACT.
// ---------------------------------------------------------------------------
#define HROWS 32
__global__ __launch_bounds__(64)
void hash_kernel(const float* __restrict__ q,
                 const float* __restrict__ k,
                 const float* __restrict__ proj) {
    __shared__ float  pjs[NPROJ][DIM];
    __shared__ float4 buf[2][HROWS * 16];
    const int t = threadIdx.x;
    for (int i = t; i < DIM * NPROJ; i += 64)
        pjs[i % NPROJ][i / NPROJ] = proj[i];

    const float4* qs = (const float4*)q + (size_t)blockIdx.x * (HROWS * 16);
    const float4* ks = (const float4*)k + (size_t)blockIdx.x * (HROWS * 16);
    const uint32_t b0 = smem_u32(&buf[0][0]);
    const uint32_t b1 = smem_u32(&buf[1][0]);
    for (int i = t; i < HROWS * 16; i += 64) {
        const int row = i >> 4, u = i & 15;
        const uint32_t off = (uint32_t)(row * 16 + (u ^ (row & 7))) * 16u;
        cpasync16(b0 + off, qs + i);
        cpasync16(b1 + off, ks + i);
    }
    cpasync_commit();
    cpasync_wait0();
    __syncthreads();

    const int which = t >> 5;          // warp 0: q rows, warp 1: k rows
    const int r0 = t & 31;
    const float4* mybuf = buf[which];

    float xr[DIM];
#pragma unroll
    for (int u = 0; u < 16; u++) {
        float4 f = mybuf[r0 * 16 + (u ^ (r0 & 7))];
        xr[4 * u] = f.x; xr[4 * u + 1] = f.y;
        xr[4 * u + 2] = f.z; xr[4 * u + 3] = f.w;
    }
    int code = 0;
#pragma unroll 1
    for (int r = 0; r < NPROJ; r++) {
        float a[32];
#pragma unroll
        for (int l = 0; l < 16; l++) {
            float4 p4 = *(const float4*)&pjs[r][4 * l];
            a[2 * l]     = xr[4 * l]     * p4.x + xr[4 * l + 1] * p4.y;
            a[2 * l + 1] = xr[4 * l + 2] * p4.z + xr[4 * l + 3] * p4.w;
        }
#pragma unroll
        for (int off = 16; off > 0; off >>= 1)
#pragma unroll
            for (int i = 0; i < 32; i++)
                if (i < off) a[i] += a[i + off];
        code |= (a[0] > 0.0f ? 1 : 0) << r;
    }
    g_hash[which][blockIdx.x * HROWS + r0] = (unsigned char)(code ^ (code >> 1));
}

// ---------------------------------------------------------------------------
// stable counting sort (validated, unchanged)
// ---------------------------------------------------------------------------
__global__ void sort_kernel() {
    __shared__ unsigned short seg[NSEG * ST];
    __shared__ int base[NBUCK];
    __shared__ int tot[NBUCK];
    const int which = blockIdx.x >> 5;
    const int bh = blockIdx.x & 31;
    const int t = threadIdx.x;
    const unsigned char* hp = g_hash[which] + bh * NSEQ;
    int* op = g_idx[which] + bh * NSEQ;

    uint32_t myb[16];
    {
        const uint4* p4 = (const uint4*)(hp + t * SEGLEN);
#pragma unroll
        for (int u = 0; u < 4; u++) {
            uint4 x = p4[u];
            myb[4 * u] = x.x; myb[4 * u + 1] = x.y;
            myb[4 * u + 2] = x.z; myb[4 * u + 3] = x.w;
        }
    }
    for (int i = t; i < NSEG * ST; i += NSEG) seg[i] = 0;
    __syncthreads();
    {
        unsigned short* row = seg + t * ST;
#pragma unroll 1
        for (int k2 = 0; k2 < SEGLEN; k2++) {
            int vv = (myb[k2 >> 2] >> ((k2 & 3) * 8)) & 0xff;
            row[vv]++;
        }
    }
    __syncthreads();
    {
        int run = 0;
        for (int s = 0; s < NSEG; s++) {
            int c = seg[s * ST + t];
            seg[s * ST + t] = (unsigned short)run;
            run += c;
        }
        tot[t] = run;
    }
    __syncthreads();
    if (t == 0) {
        int run = 0;
        for (int vv = 0; vv < NBUCK; vv++) { base[vv] = run; run += tot[vv]; }
    }
    __syncthreads();
    {
        unsigned short* row = seg + t * ST;
        const int b0 = t * SEGLEN;
#pragma unroll 1
        for (int k2 = 0; k2 < SEGLEN; k2++) {
            int vv = (myb[k2 >> 2] >> ((k2 & 3) * 8)) & 0xff;
            op[base[vv] + row[vv]] = b0 + k2;
            row[vv]++;
        }
    }
}

// ---------------------------------------------------------------------------
// conv: materialize sorted K/V as fp16 (validated, unchanged)
// ---------------------------------------------------------------------------
__global__ __launch_bounds__(256)
void conv_kernel(const float* __restrict__ k, const float* __restrict__ v) {
    const int bh = blockIdx.y;
    const int t = threadIdx.x;
    const int j = t >> 2, sub = t & 3;
    const int srow = blockIdx.x * 64 + j;
    const size_t bhBase = (size_t)bh * NSEQ;
    const int krow = g_idx[1][bhBase + srow];
    const float4* ks = (const float4*)(k + (bhBase + krow) * DIM + sub * 16);
    const float4* vs = (const float4*)(v + (bhBase + krow) * DIM + sub * 16);

    uint4* kd = (uint4*)(g_kh + (bhBase + srow) * DIM) + sub * 2;
    uint4* vd = (uint4*)(g_vh + (bhBase + srow) * DIM) + sub * 2;
#pragma unroll
    for (int hf = 0; hf < 2; hf++) {
        float4 a = ks[2 * hf], b = ks[2 * hf + 1];
        half2 h0 = __floats2half2_rn(a.x, a.y), h1 = __floats2half2_rn(a.z, a.w);
        half2 h2 = __floats2half2_rn(b.x, b.y), h3 = __floats2half2_rn(b.z, b.w);
        uint4 pk = {*(uint32_t*)&h0, *(uint32_t*)&h1, *(uint32_t*)&h2, *(uint32_t*)&h3};
        kd[hf] = pk;
        a = vs[2 * hf]; b = vs[2 * hf + 1];
        h0 = __floats2half2_rn(a.x, a.y); h1 = __floats2half2_rn(a.z, a.w);
        h2 = __floats2half2_rn(b.x, b.y); h3 = __floats2half2_rn(b.z, b.w);
        uint4 pv = {*(uint32_t*)&h0, *(uint32_t*)&h1, *(uint32_t*)&h2, *(uint32_t*)&h3};
        vd[hf] = pv;
    }
}

// ---------------------------------------------------------------------------
// fused attention: grid (64 q-halves, 32 bh), 128 threads (4 warps x 32 rows),
// 2 CTAs/SM.  S/softmax/PV interleaved per 16-key step (jj) — identical
// arithmetic order to the round-16 kernel, better pipe overlap.
// ---------------------------------------------------------------------------
__global__ __launch_bounds__(128, 2)
void attn_kernel(const float* __restrict__ q, const int* __restrict__ sampled,
                 float* __restrict__ out) {
    __shared__ __align__(128) char KsmB[2 * 8192];
    __shared__ __align__(128) char VsmB[2 * 8192];
    __shared__ float addv[2][64];

    const int tid  = threadIdx.x;
    const int w    = tid >> 5;          // 0..3
    const int lane = tid & 31;
    const int qh2  = blockIdx.x;        // 0..63 (128-query half-block)
    const int qb   = qh2 >> 1;          // sorted key block
    const int bh   = blockIdx.y;
    const size_t bhBase = (size_t)bh * NSEQ;
    const int* qidx = g_idx[0] + bhBase;
    const int* smp  = sampled + bh * 256;

    const uint32_t Ksm = smem_u32(KsmB);
    const uint32_t Vsm = smem_u32(VsmB);

    // ---- Q fragments: warp w owns rows [32w, 32w+32): tiles t0, t1 ----
    const int rt = 32 * w + (lane >> 2);
    int qrow[2][2];
    qrow[0][0] = qidx[qh2 * 128 + rt];
    qrow[0][1] = qidx[qh2 * 128 + rt + 8];
    qrow[1][0] = qidx[qh2 * 128 + rt + 16];
    qrow[1][1] = qidx[qh2 * 128 + rt + 24];
    const float qsc = 0.125f * LOG2E;

    uint32_t qh[2][4][4];
#pragma unroll
    for (int tt = 0; tt < 2; tt++) {
        const float* q0p = q + (bhBase + qrow[tt][0]) * DIM;
        const float* q1p = q + (bhBase + qrow[tt][1]) * DIM;
#pragma unroll
        for (int s = 0; s < 4; s++) {
            const int d = 16 * s + (lane & 3) * 2;
            float2 f00 = *(const float2*)(q0p + d);
            float2 f10 = *(const float2*)(q1p + d);
            float2 f01 = *(const float2*)(q0p + d + 8);
            float2 f11 = *(const float2*)(q1p + d + 8);
            half2 h;
            h = __floats2half2_rn(f00.x * qsc, f00.y * qsc); qh[tt][s][0] = *(uint32_t*)&h;
            h = __floats2half2_rn(f10.x * qsc, f10.y * qsc); qh[tt][s][1] = *(uint32_t*)&h;
            h = __floats2half2_rn(f01.x * qsc, f01.y * qsc); qh[tt][s][2] = *(uint32_t*)&h;
            h = __floats2half2_rn(f11.x * qsc, f11.y * qsc); qh[tt][s][3] = *(uint32_t*)&h;
        }
    }

    // ---- load lane mapping: 2 threads per key row, 64B halves ----
    const int j   = tid >> 1;          // key row 0..63
    const int sub = tid & 1;           // 64B half (32 halfs)

    float O[2][8][4];
#pragma unroll
    for (int tt = 0; tt < 2; tt++)
#pragma unroll
        for (int g = 0; g < 8; g++)
#pragma unroll
            for (int e = 0; e < 4; e++) O[tt][g][e] = 0.0f;
    float lsum[2][2] = {{0.0f, 0.0f}, {0.0f, 0.0f}};

    // ---- issue chunk 0 ----
    {
        const int srow = qb * 256 + j;
        const __half* ksrc = g_kh + (bhBase + srow) * DIM + sub * 32;
        const __half* vsrc = g_vh + (bhBase + srow) * DIM + sub * 32;
#pragma unroll
        for (int u = 0; u < 4; u++) {
            const uint32_t o0 = swz((uint32_t)(j * 128 + sub * 64 + u * 16));
            cpasync16(Ksm + o0, ksrc + u * 8);
            cpasync16(Vsm + o0, vsrc + u * 8);
        }
        if (sub == 0) addv[0][j] = -M_FIX * LOG2E;
        cpasync_commit();
    }
    cpasync_wait0();
    __syncthreads();

#pragma unroll 1
    for (int c = 0; c < 8; c++) {
        // ---- issue chunk c+1 into the other buffer ----
        if (c < 7) {
            const int kk = (c + 1) * 64 + j;
            int srow; float ad;
            if (kk < 256) { srow = qb * 256 + kk; ad = -M_FIX * LOG2E; }
            else {
                int sj = smp[kk - 256];
                srow = sj;
                ad = ((sj >> 8) == qb) ? BIGNEG : ((LOG32 - M_FIX) * LOG2E);
            }
            const __half* ksrc = g_kh + (bhBase + srow) * DIM + sub * 32;
            const __half* vsrc = g_vh + (bhBase + srow) * DIM + sub * 32;
            const uint32_t bb = (uint32_t)((c + 1) & 1) * 8192;
#pragma unroll
            for (int u = 0; u < 4; u++) {
                const uint32_t o0 = bb + swz((uint32_t)(j * 128 + sub * 64 + u * 16));
                cpasync16(Ksm + o0, ksrc + u * 8);
                cpasync16(Vsm + o0, vsrc + u * 8);
            }
            if (sub == 0) addv[(c + 1) & 1][j] = ad;
            cpasync_commit();
        }

        const uint32_t Kb = Ksm + (uint32_t)(c & 1) * 8192;
        const uint32_t Vb = Vsm + (uint32_t)(c & 1) * 8192;
        const float* av = addv[c & 1];

        // ---- interleaved: per 16-key step, S + softmax then PV ----
#pragma unroll
        for (int jj = 0; jj < 4; jj++) {
            uint32_t P01[2][2], P23[2][2];   // [tile][group-in-step]
#pragma unroll
            for (int gp = 0; gp < 2; gp++) {
                const int g = 2 * jj + gp;
                uint32_t kb[8];
                const uint32_t key = 8u * g + (lane & 7);
                const uint32_t dv  = ((uint32_t)(lane >> 3) & 3u) * 8u;
                ldsm4(kb,     Kb + swz(key * 128 + dv * 2));
                ldsm4(kb + 4, Kb + swz(key * 128 + (32 + dv) * 2));
                const int n0 = 8 * g + (lane & 3) * 2;
                const float av0 = av[n0], av1 = av[n0 + 1];
#pragma unroll
                for (int tt = 0; tt < 2; tt++) {
                    float S[4] = {0.0f, 0.0f, 0.0f, 0.0f};
#pragma unroll
                    for (int s = 0; s < 4; s++)
                        mma16816(S, qh[tt][s], kb[2 * s], kb[2 * s + 1]);
                    float e0 = ex2f(S[0] + av0);
                    float e1 = ex2f(S[1] + av1);
                    float e2 = ex2f(S[2] + av0);
                    float e3 = ex2f(S[3] + av1);
                    lsum[tt][0] += e0 + e1;
                    lsum[tt][1] += e2 + e3;
                    half2 h01 = __floats2half2_rn(e0, e1);
                    half2 h23 = __floats2half2_rn(e2, e3);
                    P01[tt][gp] = *(uint32_t*)&h01;
                    P23[tt][gp] = *(uint32_t*)&h23;
                }
            }
            // PV for this 16-key step
            const uint32_t key = 16u * jj + ((uint32_t)lane & 15u);
            const uint32_t dof = ((uint32_t)(lane >> 4) & 1u) * 8u;
            uint32_t A0[4] = {P01[0][0], P23[0][0], P01[0][1], P23[0][1]};
            uint32_t A1[4] = {P01[1][0], P23[1][0], P01[1][1], P23[1][1]};
#pragma unroll
            for (int dg = 0; dg < 4; dg++) {
                uint32_t vb[4];
                ldsm4t(vb, Vb + swz(key * 128 + (16u * dg + dof) * 2));
                mma16816(O[0][2 * dg],     A0, vb[0], vb[1]);
                mma16816(O[0][2 * dg + 1], A0, vb[2], vb[3]);
                mma16816(O[1][2 * dg],     A1, vb[0], vb[1]);
                mma16816(O[1][2 * dg + 1], A1, vb[2], vb[3]);
            }
        }

        if (c < 7) cpasync_wait0();
        __syncthreads();
    }

    // ---- epilogue ----
#pragma unroll
    for (int tt = 0; tt < 2; tt++) {
        float l0 = lsum[tt][0], l1 = lsum[tt][1];
        l0 += __shfl_xor_sync(0xffffffffu, l0, 1);
        l0 += __shfl_xor_sync(0xffffffffu, l0, 2);
        l1 += __shfl_xor_sync(0xffffffffu, l1, 1);
        l1 += __shfl_xor_sync(0xffffffffu, l1, 2);
        const float inv0 = 1.0f / l0;
        const float inv1 = 1.0f / l1;
        float* o0p = out + (bhBase + qrow[tt][0]) * DIM;
        float* o1p = out + (bhBase + qrow[tt][1]) * DIM;
#pragma unroll
        for (int g = 0; g < 8; g++) {
            const int n0 = 8 * g + (lane & 3) * 2;
            float2 a = {O[tt][g][0] * inv0, O[tt][g][1] * inv0};
            float2 b = {O[tt][g][2] * inv1, O[tt][g][3] * inv1};
            *(float2*)(o0p + n0) = a;
            *(float2*)(o1p + n0) = b;
        }
    }
}

// ---------------------------------------------------------------------------
extern "C" void kernel_launch(void* const* d_in, const int* in_sizes, int n_in,
                              void* d_out, int out_size) {
    (void)in_sizes; (void)n_in; (void)out_size;
    const float* q    = (const float*)d_in[0];
    const float* k    = (const float*)d_in[1];
    const float* v    = (const float*)d_in[2];
    const float* proj = (const float*)d_in[3];
    const int*   smp  = (const int*)d_in[4];
    float* out = (float*)d_out;

    hash_kernel<<<(BH * NSEQ) / HROWS, 64>>>(q, k, proj);
    sort_kernel<<<64, 128>>>();
    conv_kernel<<<dim3(NSEQ / 64, BH), 256>>>(k, v);
    attn_kernel<<<dim3(64, 32), 128>>>(q, smp, out);
}